// round 5
// baseline (speedup 1.0000x reference)
#include <cuda_runtime.h>
#include <math.h>

#define NN 100000
#define NE 1600000
#define HID 32
#define KIN 128

// ---------------- device scratch (allocation-free: __device__ globals) ----------------
__device__ float g_deg[3 * NN];          // weighted in-degree (w/o self loop)
__device__ float g_dinv[3 * NN];         // rsqrt(deg + 1)
__device__ int   g_cnt[3 * NN];          // per-dest edge counts
__device__ int   g_cur[3 * NN];          // scatter cursors
__device__ int   g_rp[3 * NN + 1];       // exclusive scan of g_cnt (global CSR rowptr)
__device__ int   g_part[256];            // scan partials
__device__ int2  g_edges[3 * NE];        // CSR-ordered (src, norm-as-int) per dest
__device__ float g_feat[3][NN * HID];    // xw_g (layer1) then hw_g (layer2)
__device__ float g_h[NN * HID];          // combined hidden
__device__ int   g_is64;                 // edge index dtype flag

// ---------------- dtype detection: int64 vs int32 edge indices ----------------
__global__ void k_detect(const long long* ei) {
    __shared__ int ok;
    if (threadIdx.x == 0) ok = 1;
    __syncthreads();
    for (int i = threadIdx.x; i < 4096; i += 256) {
        long long v = ei[i];
        if (v < 0 || v >= NN) ok = 0;   // int32 data read as int64 -> out-of-range values
    }
    __syncthreads();
    if (threadIdx.x == 0) g_is64 = ok;
}

__device__ __forceinline__ int load_idx(const void* eiv, long long pos) {
    if (g_is64) return (int)((const long long*)eiv)[pos];
    return ((const int*)eiv)[pos];
}

// ---------------- zero scratch ----------------
__global__ void k_zero() {
    int i = blockIdx.x * blockDim.x + threadIdx.x;
    if (i < 3 * NN) { g_deg[i] = 0.f; g_cnt[i] = 0; g_cur[i] = 0; }
}

// ---------------- degree + count (all 3 graphs, grid.y = graph) ----------------
__global__ void k_count(const void* ei0, const void* ei1, const void* ei2,
                        const float* ea0, const float* ea1, const float* ea2) {
    int i = blockIdx.x * blockDim.x + threadIdx.x;
    if (i >= NE) return;
    int g = blockIdx.y;
    const void* eiv = (g == 0) ? ei0 : (g == 1) ? ei1 : ei2;
    const float* ea = (g == 0) ? ea0 : (g == 1) ? ea1 : ea2;
    int c = load_idx(eiv, (long long)NE + i);
    atomicAdd(&g_deg[g * NN + c], ea[i]);
    atomicAdd(&g_cnt[g * NN + c], 1);
}

__global__ void k_dinv() {
    int i = blockIdx.x * blockDim.x + threadIdx.x;
    if (i < 3 * NN) g_dinv[i] = rsqrtf(g_deg[i] + 1.0f);
}

// ---------------- 3-kernel exclusive scan over g_cnt[3*NN] ----------------
#define SCAN_CHUNK 2048
__global__ void k_scanA() {
    int base = blockIdx.x * SCAN_CHUNK;
    int t = threadIdx.x;
    int s = 0;
    #pragma unroll
    for (int k = 0; k < 8; k++) {
        int idx = base + t * 8 + k;
        if (idx < 3 * NN) s += g_cnt[idx];
    }
    __shared__ int sh[256];
    sh[t] = s; __syncthreads();
    for (int off = 128; off; off >>= 1) {
        if (t < off) sh[t] += sh[t + off];
        __syncthreads();
    }
    if (t == 0) g_part[blockIdx.x] = sh[0];
}

__global__ void k_scanB(int nb) {
    int run = 0;
    for (int b = 0; b < nb; b++) { int v = g_part[b]; g_part[b] = run; run += v; }
    g_rp[3 * NN] = run;   // == 3*NE
}

__global__ void k_scanC() {
    int b = blockIdx.x, t = threadIdx.x;
    int lane = t & 31, w = t >> 5;
    int base = b * SCAN_CHUNK + t * 8;
    int v[8]; int s = 0;
    #pragma unroll
    for (int k = 0; k < 8; k++) {
        int idx = base + k;
        v[k] = (idx < 3 * NN) ? g_cnt[idx] : 0;
    }
    #pragma unroll
    for (int k = 0; k < 8; k++) { int tmp = v[k]; v[k] = s; s += tmp; }
    int inc = s;
    #pragma unroll
    for (int off = 1; off < 32; off <<= 1) {
        int nv = __shfl_up_sync(0xffffffffu, inc, off);
        if (lane >= off) inc += nv;
    }
    int texc = inc - s;
    __shared__ int wsum[8];
    if (lane == 31) wsum[w] = inc;
    __syncthreads();
    if (t == 0) {
        int run = 0;
        for (int i = 0; i < 8; i++) { int tmp = wsum[i]; wsum[i] = run; run += tmp; }
    }
    __syncthreads();
    int off0 = g_part[b] + wsum[w] + texc;
    #pragma unroll
    for (int k = 0; k < 8; k++) {
        int idx = base + k;
        if (idx < 3 * NN) g_rp[idx] = off0 + v[k];
    }
}

// ---------------- scatter edges into CSR order (all 3 graphs) ----------------
__global__ void k_scatter(const void* ei0, const void* ei1, const void* ei2,
                          const float* ea0, const float* ea1, const float* ea2) {
    int i = blockIdx.x * blockDim.x + threadIdx.x;
    if (i >= NE) return;
    int g = blockIdx.y;
    const void* eiv = (g == 0) ? ei0 : (g == 1) ? ei1 : ei2;
    const float* ea = (g == 0) ? ea0 : (g == 1) ? ea1 : ea2;
    int r = load_idx(eiv, i);
    int c = load_idx(eiv, (long long)NE + i);
    float nrm = g_dinv[g * NN + r] * ea[i] * g_dinv[g * NN + c];
    int pos = g_rp[g * NN + c] + atomicAdd(&g_cur[g * NN + c], 1);
    g_edges[pos] = make_int2(r, __float_as_int(nrm));
}

// ---------------- dense GEMM: Y[N,32] = X[N,K] @ W[K,32] ----------------
template<int K, bool USEH>
__global__ void __launch_bounds__(256) k_gemm(const float* __restrict__ Xext,
                                              const float* __restrict__ Wm, int gdst) {
    __shared__ float Wsh[K * HID];
    __shared__ float Xs[32 * (K + 4)];
    const float* X = USEH ? (const float*)g_h : Xext;
    float* Y = g_feat[gdst];
    int t = threadIdx.x;
    for (int i = t; i < K * HID; i += 256) Wsh[i] = Wm[i];
    const float* xb = X + (size_t)blockIdx.x * 32 * K;
    for (int i = t; i < 32 * K; i += 256) {
        int r = i / K, k = i - r * K;
        Xs[r * (K + 4) + k] = xb[i];
    }
    __syncthreads();
    int w = t >> 5, lane = t & 31;
    int r = w * 4 + (lane >> 3);
    int cq = lane & 7;
    const float* xrow = &Xs[r * (K + 4)];
    float4 acc = make_float4(0.f, 0.f, 0.f, 0.f);
    #pragma unroll 16
    for (int k = 0; k < K; k++) {
        float xk = xrow[k];
        float4 wv = *(const float4*)&Wsh[k * HID + cq * 4];
        acc.x = fmaf(xk, wv.x, acc.x);
        acc.y = fmaf(xk, wv.y, acc.y);
        acc.z = fmaf(xk, wv.z, acc.z);
        acc.w = fmaf(xk, wv.w, acc.w);
    }
    size_t gr = (size_t)blockIdx.x * 32 + r;
    *(float4*)&Y[gr * HID + cq * 4] = acc;
}

// ---------------- CSR gather for one node segment (lane j = feature dim) ----------------
__device__ __forceinline__ float gather_seg(const float* __restrict__ H, int s, int e2, int j) {
    float a = 0.f;
    int e = s;
    for (; e + 4 <= e2; e += 4) {
        int2 p0 = g_edges[e + 0];
        int2 p1 = g_edges[e + 1];
        int2 p2 = g_edges[e + 2];
        int2 p3 = g_edges[e + 3];
        float v0 = __ldg(&H[p0.x * HID + j]);
        float v1 = __ldg(&H[p1.x * HID + j]);
        float v2 = __ldg(&H[p2.x * HID + j]);
        float v3 = __ldg(&H[p3.x * HID + j]);
        a = fmaf(__int_as_float(p0.y), v0, a);
        a = fmaf(__int_as_float(p1.y), v1, a);
        a = fmaf(__int_as_float(p2.y), v2, a);
        a = fmaf(__int_as_float(p3.y), v3, a);
    }
    for (; e < e2; e++) {
        int2 p = g_edges[e];
        a = fmaf(__int_as_float(p.y), __ldg(&H[p.x * HID + j]), a);
    }
    return a;
}

// ---------------- layer 1: 3x conv + relu + attention + combine ----------------
__global__ void __launch_bounds__(256) k_conv1(const float* __restrict__ b0,
                                               const float* __restrict__ b1,
                                               const float* __restrict__ b2,
                                               const float* __restrict__ attw,
                                               float* __restrict__ wout) {
    int c = blockIdx.x * 8 + (threadIdx.x >> 5);
    int j = threadIdx.x & 31;
    if (c >= NN) return;
    float acc[3];
    #pragma unroll
    for (int g = 0; g < 3; g++) {
        const float* H = g_feat[g];
        int s = g_rp[g * NN + c], e2 = g_rp[g * NN + c + 1];
        float a = gather_seg(H, s, e2, j);
        float di = g_dinv[g * NN + c];
        a = fmaf(di * di, H[c * HID + j], a);   // self loop (weight 1)
        acc[g] = a;
    }
    acc[0] += b0[j]; acc[1] += b1[j]; acc[2] += b2[j];
    acc[0] = fmaxf(acc[0], 0.f);
    acc[1] = fmaxf(acc[1], 0.f);
    acc[2] = fmaxf(acc[2], 0.f);
    float attj = attw[j];
    float cf[3];
    #pragma unroll
    for (int g = 0; g < 3; g++) {
        float v = acc[g] * attj;
        v += __shfl_xor_sync(0xffffffffu, v, 16);
        v += __shfl_xor_sync(0xffffffffu, v, 8);
        v += __shfl_xor_sync(0xffffffffu, v, 4);
        v += __shfl_xor_sync(0xffffffffu, v, 2);
        v += __shfl_xor_sync(0xffffffffu, v, 1);
        v = (v > 0.f) ? v : 0.01f * v;          // jax.nn.leaky_relu default slope 0.01
        cf[g] = expf(v);
    }
    float inv = 1.0f / (cf[0] + cf[1] + cf[2]);
    float w0 = cf[0] * inv, w1 = cf[1] * inv, w2 = cf[2] * inv;
    g_h[c * HID + j] = w0 * acc[0] + w1 * acc[1] + w2 * acc[2];
    if (j == 0) { wout[c] = w0; wout[NN + c] = w1; wout[2 * NN + c] = w2; }
}

// ---------------- layer 2: sum of 3 convs ----------------
__global__ void __launch_bounds__(256) k_conv2(const float* __restrict__ bo0,
                                               const float* __restrict__ bo1,
                                               const float* __restrict__ bo2,
                                               float* __restrict__ out) {
    int c = blockIdx.x * 8 + (threadIdx.x >> 5);
    int j = threadIdx.x & 31;
    if (c >= NN) return;
    float a = bo0[j] + bo1[j] + bo2[j];
    #pragma unroll
    for (int g = 0; g < 3; g++) {
        const float* H = g_feat[g];
        int s = g_rp[g * NN + c], e2 = g_rp[g * NN + c + 1];
        a += gather_seg(H, s, e2, j);
        float di = g_dinv[g * NN + c];
        a = fmaf(di * di, H[c * HID + j], a);
    }
    out[c * HID + j] = a;
}

// ---------------- host launch ----------------
extern "C" void kernel_launch(void* const* d_in, const int* in_sizes, int n_in,
                              void* d_out, int out_size) {
    const float *x[3], *ea[3], *W[3], *b[3], *Wo[3], *bo[3], *attw;
    const void *ei[3];

    bool interleaved = (in_sizes[1] == 2 * NE);   // dict order: x1,ei1,ea1,W1,b1,Wo1,bo1,...
    if (interleaved) {
        for (int g = 0; g < 3; g++) {
            int base = g * 7;
            x[g]  = (const float*)d_in[base + 0];
            ei[g] = d_in[base + 1];
            ea[g] = (const float*)d_in[base + 2];
            W[g]  = (const float*)d_in[base + 3];
            b[g]  = (const float*)d_in[base + 4];
            Wo[g] = (const float*)d_in[base + 5];
            bo[g] = (const float*)d_in[base + 6];
        }
        attw = (const float*)d_in[21];
    } else {                                       // signature order: x1,x2,x3,ei1..ei3,...
        for (int g = 0; g < 3; g++) {
            x[g]  = (const float*)d_in[g];
            ei[g] = d_in[3 + g];
            ea[g] = (const float*)d_in[6 + g];
            W[g]  = (const float*)d_in[9 + g];
            b[g]  = (const float*)d_in[12 + g];
            Wo[g] = (const float*)d_in[15 + g];
            bo[g] = (const float*)d_in[18 + g];
        }
        attw = (const float*)d_in[21];
    }

    float* out  = (float*)d_out;
    float* wout = out + (size_t)NN * HID;

    const int eblocks = (NE + 255) / 256;
    const int nblocks3N = (3 * NN + 255) / 256;
    const int NB = (3 * NN + SCAN_CHUNK - 1) / SCAN_CHUNK;   // 147
    const int gemm_blocks = NN / 32;                          // 3125
    const int conv_blocks = (NN + 7) / 8;                     // 12500
    dim3 egrid(eblocks, 3, 1);

    k_detect<<<1, 256>>>((const long long*)ei[0]);
    k_zero<<<nblocks3N, 256>>>();
    k_count<<<egrid, 256>>>(ei[0], ei[1], ei[2], ea[0], ea[1], ea[2]);
    k_dinv<<<nblocks3N, 256>>>();
    k_scanA<<<NB, 256>>>();
    k_scanB<<<1, 1>>>(NB);
    k_scanC<<<NB, 256>>>();
    k_scatter<<<egrid, 256>>>(ei[0], ei[1], ei[2], ea[0], ea[1], ea[2]);
    for (int g = 0; g < 3; g++) k_gemm<KIN, false><<<gemm_blocks, 256>>>(x[g], W[g], g);
    k_conv1<<<conv_blocks, 256>>>(b[0], b[1], b[2], attw, wout);
    for (int g = 0; g < 3; g++) k_gemm<HID, true><<<gemm_blocks, 256>>>(nullptr, Wo[g], g);
    k_conv2<<<conv_blocks, 256>>>(bo[0], bo[1], bo[2], out);
}

// round 8
// speedup vs baseline: 1.0419x; 1.0419x over previous
#include <cuda_runtime.h>
#include <math.h>

#define NN 100000
#define NE 1600000
#define HID 32
#define KIN 128

// ---------------- device scratch (allocation-free: __device__ globals) ----------------
__device__ float g_deg[3 * NN];          // weighted in-degree (w/o self loop)
__device__ float g_dinv[3 * NN];         // rsqrt(deg + 1)
__device__ int   g_cnt[3 * NN];          // per-dest edge counts
__device__ int   g_rp[3 * NN + 1];       // exclusive scan of g_cnt (global CSR rowptr)
__device__ int   g_part[256];            // scan partials
__device__ int   g_rank[3 * NE];         // edge rank within its dest (from count pass)
__device__ int2  g_srccol[3 * NE];       // int32 (src, col) per edge (from count pass)
__device__ int2  g_edges[3 * NE];        // CSR-ordered (src, norm-as-int) per dest
__device__ float g_feat[3][NN * HID];    // xw_g (layer1) then hw_g (layer2)
__device__ float g_h[NN * HID];          // combined hidden
__device__ int   g_is64;                 // edge index dtype flag

// ---------------- init: zero scratch + dtype detect (block 0) ----------------
__global__ void k_init(const long long* ei) {
    int i = blockIdx.x * blockDim.x + threadIdx.x;
    if (i < 3 * NN) { g_deg[i] = 0.f; g_cnt[i] = 0; }
    if (blockIdx.x == 0) {
        __shared__ int ok;
        if (threadIdx.x == 0) ok = 1;
        __syncthreads();
        for (int k = threadIdx.x; k < 4096; k += 256) {
            long long v = ei[k];
            if (v < 0 || v >= NN) ok = 0;   // int32 data read as int64 -> out-of-range
        }
        __syncthreads();
        if (threadIdx.x == 0) g_is64 = ok;
    }
}

__device__ __forceinline__ int load_idx(const void* eiv, long long pos) {
    if (g_is64) return (int)((const long long*)eiv)[pos];
    return ((const int*)eiv)[pos];
}

// ---------------- pass 1 over edges: degree + count + persist rank/src/col ----------------
__global__ void k_count(const void* ei0, const void* ei1, const void* ei2,
                        const float* ea0, const float* ea1, const float* ea2) {
    int i = blockIdx.x * blockDim.x + threadIdx.x;
    if (i >= NE) return;
    int g = blockIdx.y;
    const void* eiv = (g == 0) ? ei0 : (g == 1) ? ei1 : ei2;
    const float* ea = (g == 0) ? ea0 : (g == 1) ? ea1 : ea2;
    int r = load_idx(eiv, i);
    int c = load_idx(eiv, (long long)NE + i);
    atomicAdd(&g_deg[g * NN + c], ea[i]);
    int rank = atomicAdd(&g_cnt[g * NN + c], 1);
    long long e = (long long)g * NE + i;
    g_rank[e] = rank;
    g_srccol[e] = make_int2(r, c);
}

// ---------------- scan A: per-chunk sums of g_cnt + dinv (fused, same 3N sweep) ----------
#define SCAN_CHUNK 2048
__global__ void k_scanA() {
    int base = blockIdx.x * SCAN_CHUNK;
    int t = threadIdx.x;
    int s = 0;
    #pragma unroll
    for (int k = 0; k < 8; k++) {
        int idx = base + t * 8 + k;
        if (idx < 3 * NN) {
            s += g_cnt[idx];
            g_dinv[idx] = rsqrtf(g_deg[idx] + 1.0f);
        }
    }
    __shared__ int sh[256];
    sh[t] = s; __syncthreads();
    for (int off = 128; off; off >>= 1) {
        if (t < off) sh[t] += sh[t + off];
        __syncthreads();
    }
    if (t == 0) g_part[blockIdx.x] = sh[0];
}

// ---------------- scan B: one-block shuffle exclusive scan of partials ----------------
__global__ void k_scanB(int nb) {
    int t = threadIdx.x, lane = t & 31, w = t >> 5;
    int v = (t < nb) ? g_part[t] : 0;
    int inc = v;
    #pragma unroll
    for (int off = 1; off < 32; off <<= 1) {
        int nv = __shfl_up_sync(0xffffffffu, inc, off);
        if (lane >= off) inc += nv;
    }
    __shared__ int ws[8];
    if (lane == 31) ws[w] = inc;
    __syncthreads();
    if (t == 0) {
        int run = 0;
        #pragma unroll
        for (int i = 0; i < 8; i++) { int tmp = ws[i]; ws[i] = run; run += tmp; }
    }
    __syncthreads();
    int exc = ws[w] + inc - v;
    if (t < nb) g_part[t] = exc;
    if (t == nb - 1) g_rp[3 * NN] = exc + v;   // == 3*NE
}

// ---------------- scan C: per-chunk exclusive scan -> rowptr ----------------
__global__ void k_scanC() {
    int b = blockIdx.x, t = threadIdx.x;
    int lane = t & 31, w = t >> 5;
    int base = b * SCAN_CHUNK + t * 8;
    int v[8]; int s = 0;
    #pragma unroll
    for (int k = 0; k < 8; k++) {
        int idx = base + k;
        v[k] = (idx < 3 * NN) ? g_cnt[idx] : 0;
    }
    #pragma unroll
    for (int k = 0; k < 8; k++) { int tmp = v[k]; v[k] = s; s += tmp; }
    int inc = s;
    #pragma unroll
    for (int off = 1; off < 32; off <<= 1) {
        int nv = __shfl_up_sync(0xffffffffu, inc, off);
        if (lane >= off) inc += nv;
    }
    int texc = inc - s;
    __shared__ int wsum[8];
    if (lane == 31) wsum[w] = inc;
    __syncthreads();
    if (t == 0) {
        int run = 0;
        #pragma unroll
        for (int i = 0; i < 8; i++) { int tmp = wsum[i]; wsum[i] = run; run += tmp; }
    }
    __syncthreads();
    int off0 = g_part[b] + wsum[w] + texc;
    #pragma unroll
    for (int k = 0; k < 8; k++) {
        int idx = base + k;
        if (idx < 3 * NN) g_rp[idx] = off0 + v[k];
    }
}

// ---------------- pass 2 over edges: atomic-free scatter into CSR order ----------------
__global__ void k_scatter(const float* ea0, const float* ea1, const float* ea2) {
    int i = blockIdx.x * blockDim.x + threadIdx.x;
    if (i >= NE) return;
    int g = blockIdx.y;
    const float* ea = (g == 0) ? ea0 : (g == 1) ? ea1 : ea2;
    long long e = (long long)g * NE + i;
    int2 sc = g_srccol[e];
    float nrm = g_dinv[g * NN + sc.x] * ea[i] * g_dinv[g * NN + sc.y];
    int pos = g_rp[g * NN + sc.y] + g_rank[e];
    g_edges[pos] = make_int2(sc.x, __float_as_int(nrm));
}

// ---------------- dense GEMM: Y[N,32] = X[N,K] @ W[K,32] ----------------
template<int K, bool USEH>
__global__ void __launch_bounds__(256) k_gemm(const float* __restrict__ Xext,
                                              const float* __restrict__ Wm, int gdst) {
    __shared__ float Wsh[K * HID];
    __shared__ float Xs[32 * (K + 4)];
    const float* X = USEH ? (const float*)g_h : Xext;
    float* Y = g_feat[gdst];
    int t = threadIdx.x;
    for (int i = t; i < K * HID; i += 256) Wsh[i] = Wm[i];
    const float* xb = X + (size_t)blockIdx.x * 32 * K;
    for (int i = t; i < 32 * K; i += 256) {
        int r = i / K, k = i - r * K;
        Xs[r * (K + 4) + k] = xb[i];
    }
    __syncthreads();
    int w = t >> 5, lane = t & 31;
    int r = w * 4 + (lane >> 3);
    int cq = lane & 7;
    const float* xrow = &Xs[r * (K + 4)];
    float4 acc = make_float4(0.f, 0.f, 0.f, 0.f);
    #pragma unroll 16
    for (int k = 0; k < K; k++) {
        float xk = xrow[k];
        float4 wv = *(const float4*)&Wsh[k * HID + cq * 4];
        acc.x = fmaf(xk, wv.x, acc.x);
        acc.y = fmaf(xk, wv.y, acc.y);
        acc.z = fmaf(xk, wv.z, acc.z);
        acc.w = fmaf(xk, wv.w, acc.w);
    }
    size_t gr = (size_t)blockIdx.x * 32 + r;
    *(float4*)&Y[gr * HID + cq * 4] = acc;
}

// ---------------- CSR gather, unrolled x8 for MLP (lane j = feature dim) ----------------
__device__ __forceinline__ float gather_seg(const float* __restrict__ H, int s, int e2, int j) {
    float a = 0.f;
    int e = s;
    for (; e + 8 <= e2; e += 8) {
        int2 p[8];
        #pragma unroll
        for (int k = 0; k < 8; k++) p[k] = g_edges[e + k];
        float v[8];
        #pragma unroll
        for (int k = 0; k < 8; k++) v[k] = __ldg(&H[p[k].x * HID + j]);
        #pragma unroll
        for (int k = 0; k < 8; k++) a = fmaf(__int_as_float(p[k].y), v[k], a);
    }
    if (e + 4 <= e2) {
        int2 p[4];
        #pragma unroll
        for (int k = 0; k < 4; k++) p[k] = g_edges[e + k];
        float v[4];
        #pragma unroll
        for (int k = 0; k < 4; k++) v[k] = __ldg(&H[p[k].x * HID + j]);
        #pragma unroll
        for (int k = 0; k < 4; k++) a = fmaf(__int_as_float(p[k].y), v[k], a);
        e += 4;
    }
    for (; e < e2; e++) {
        int2 p = g_edges[e];
        a = fmaf(__int_as_float(p.y), __ldg(&H[p.x * HID + j]), a);
    }
    return a;
}

// ---------------- layer 1: 3x conv + relu + attention + combine ----------------
__global__ void __launch_bounds__(256) k_conv1(const float* __restrict__ b0,
                                               const float* __restrict__ b1,
                                               const float* __restrict__ b2,
                                               const float* __restrict__ attw,
                                               float* __restrict__ wout) {
    int c = blockIdx.x * 8 + (threadIdx.x >> 5);
    int j = threadIdx.x & 31;
    if (c >= NN) return;
    float acc[3];
    #pragma unroll
    for (int g = 0; g < 3; g++) {
        const float* H = g_feat[g];
        int s = g_rp[g * NN + c], e2 = g_rp[g * NN + c + 1];
        float a = gather_seg(H, s, e2, j);
        float di = g_dinv[g * NN + c];
        a = fmaf(di * di, H[c * HID + j], a);   // self loop (weight 1)
        acc[g] = a;
    }
    acc[0] += b0[j]; acc[1] += b1[j]; acc[2] += b2[j];
    acc[0] = fmaxf(acc[0], 0.f);
    acc[1] = fmaxf(acc[1], 0.f);
    acc[2] = fmaxf(acc[2], 0.f);
    float attj = attw[j];
    float cf[3];
    #pragma unroll
    for (int g = 0; g < 3; g++) {
        float v = acc[g] * attj;
        v += __shfl_xor_sync(0xffffffffu, v, 16);
        v += __shfl_xor_sync(0xffffffffu, v, 8);
        v += __shfl_xor_sync(0xffffffffu, v, 4);
        v += __shfl_xor_sync(0xffffffffu, v, 2);
        v += __shfl_xor_sync(0xffffffffu, v, 1);
        v = (v > 0.f) ? v : 0.01f * v;          // jax.nn.leaky_relu default slope
        cf[g] = expf(v);
    }
    float inv = 1.0f / (cf[0] + cf[1] + cf[2]);
    float w0 = cf[0] * inv, w1 = cf[1] * inv, w2 = cf[2] * inv;
    g_h[c * HID + j] = w0 * acc[0] + w1 * acc[1] + w2 * acc[2];
    if (j == 0) { wout[c] = w0; wout[NN + c] = w1; wout[2 * NN + c] = w2; }
}

// ---------------- layer 2: sum of 3 convs ----------------
__global__ void __launch_bounds__(256) k_conv2(const float* __restrict__ bo0,
                                               const float* __restrict__ bo1,
                                               const float* __restrict__ bo2,
                                               float* __restrict__ out) {
    int c = blockIdx.x * 8 + (threadIdx.x >> 5);
    int j = threadIdx.x & 31;
    if (c >= NN) return;
    float a = bo0[j] + bo1[j] + bo2[j];
    #pragma unroll
    for (int g = 0; g < 3; g++) {
        const float* H = g_feat[g];
        int s = g_rp[g * NN + c], e2 = g_rp[g * NN + c + 1];
        a += gather_seg(H, s, e2, j);
        float di = g_dinv[g * NN + c];
        a = fmaf(di * di, H[c * HID + j], a);
    }
    out[c * HID + j] = a;
}

// ---------------- host launch ----------------
extern "C" void kernel_launch(void* const* d_in, const int* in_sizes, int n_in,
                              void* d_out, int out_size) {
    const float *x[3], *ea[3], *W[3], *b[3], *Wo[3], *bo[3], *attw;
    const void *ei[3];

    bool interleaved = (in_sizes[1] == 2 * NE);   // dict order: x1,ei1,ea1,W1,b1,Wo1,bo1,...
    if (interleaved) {
        for (int g = 0; g < 3; g++) {
            int base = g * 7;
            x[g]  = (const float*)d_in[base + 0];
            ei[g] = d_in[base + 1];
            ea[g] = (const float*)d_in[base + 2];
            W[g]  = (const float*)d_in[base + 3];
            b[g]  = (const float*)d_in[base + 4];
            Wo[g] = (const float*)d_in[base + 5];
            bo[g] = (const float*)d_in[base + 6];
        }
        attw = (const float*)d_in[21];
    } else {                                       // signature order: x1,x2,x3,ei1..ei3,...
        for (int g = 0; g < 3; g++) {
            x[g]  = (const float*)d_in[g];
            ei[g] = d_in[3 + g];
            ea[g] = (const float*)d_in[6 + g];
            W[g]  = (const float*)d_in[9 + g];
            b[g]  = (const float*)d_in[12 + g];
            Wo[g] = (const float*)d_in[15 + g];
            bo[g] = (const float*)d_in[18 + g];
        }
        attw = (const float*)d_in[21];
    }

    float* out  = (float*)d_out;
    float* wout = out + (size_t)NN * HID;

    const int eblocks = (NE + 255) / 256;
    const int nblocks3N = (3 * NN + 255) / 256;
    const int NB = (3 * NN + SCAN_CHUNK - 1) / SCAN_CHUNK;   // 147
    const int gemm_blocks = NN / 32;                          // 3125
    const int conv_blocks = (NN + 7) / 8;                     // 12500
    dim3 egrid(eblocks, 3, 1);

    k_init<<<nblocks3N, 256>>>((const long long*)ei[0]);
    k_count<<<egrid, 256>>>(ei[0], ei[1], ei[2], ea[0], ea[1], ea[2]);
    k_scanA<<<NB, 256>>>();
    k_scanB<<<1, 256>>>(NB);
    k_scanC<<<NB, 256>>>();
    k_scatter<<<egrid, 256>>>(ea[0], ea[1], ea[2]);
    for (int g = 0; g < 3; g++) k_gemm<KIN, false><<<gemm_blocks, 256>>>(x[g], W[g], g);
    k_conv1<<<conv_blocks, 256>>>(b[0], b[1], b[2], attw, wout);
    for (int g = 0; g < 3; g++) k_gemm<HID, true><<<gemm_blocks, 256>>>(nullptr, Wo[g], g);
    k_conv2<<<conv_blocks, 256>>>(bo[0], bo[1], bo[2], out);
}

// round 9
// speedup vs baseline: 1.1312x; 1.0858x over previous
#include <cuda_runtime.h>
#include <cuda_fp16.h>
#include <math.h>

#define NN 100000
#define NE 1600000
#define HID 32
#define KIN 128

// ---------------- device scratch (allocation-free: __device__ globals) ----------------
__device__ float  g_deg[3 * NN];          // weighted in-degree (w/o self loop)
__device__ float  g_dinv[3 * NN];         // rsqrt(deg + 1)
__device__ int    g_cnt[3 * NN];          // per-dest edge counts
__device__ int    g_rp[3 * NN + 1];       // exclusive scan of g_cnt (global CSR rowptr)
__device__ int    g_part[256];            // scan partials
__device__ int    g_rank[3 * NE];         // edge rank within its dest (from count pass)
__device__ int2   g_srccol[3 * NE];       // int32 (src, col) per edge (from count pass)
__device__ int2   g_edges[3 * NE];        // CSR-ordered (src, norm-as-int) per dest
__device__ __half g_feat[3][NN * HID];    // xw_g (layer1) then hw_g (layer2), fp16
__device__ float  g_h[NN * HID];          // combined hidden (fp32)
__device__ int    g_is64;                 // edge index dtype flag

// ---------------- init: zero scratch + dtype detect (block 0) ----------------
__global__ void k_init(const long long* ei) {
    int i = blockIdx.x * blockDim.x + threadIdx.x;
    if (i < 3 * NN) { g_deg[i] = 0.f; g_cnt[i] = 0; }
    if (blockIdx.x == 0) {
        __shared__ int ok;
        if (threadIdx.x == 0) ok = 1;
        __syncthreads();
        for (int k = threadIdx.x; k < 4096; k += 256) {
            long long v = ei[k];
            if (v < 0 || v >= NN) ok = 0;   // int32 data read as int64 -> out-of-range
        }
        __syncthreads();
        if (threadIdx.x == 0) g_is64 = ok;
    }
}

__device__ __forceinline__ int load_idx(const void* eiv, long long pos) {
    if (g_is64) return (int)((const long long*)eiv)[pos];
    return ((const int*)eiv)[pos];
}

// ---------------- pass 1 over edges: degree + count + persist rank/src/col ----------------
__global__ void k_count(const void* ei0, const void* ei1, const void* ei2,
                        const float* ea0, const float* ea1, const float* ea2) {
    int i = blockIdx.x * blockDim.x + threadIdx.x;
    if (i >= NE) return;
    int g = blockIdx.y;
    const void* eiv = (g == 0) ? ei0 : (g == 1) ? ei1 : ei2;
    const float* ea = (g == 0) ? ea0 : (g == 1) ? ea1 : ea2;
    int r = load_idx(eiv, i);
    int c = load_idx(eiv, (long long)NE + i);
    atomicAdd(&g_deg[g * NN + c], ea[i]);
    int rank = atomicAdd(&g_cnt[g * NN + c], 1);
    long long e = (long long)g * NE + i;
    g_rank[e] = rank;
    g_srccol[e] = make_int2(r, c);
}

// ---------------- scan A: per-chunk sums of g_cnt + dinv (fused, same 3N sweep) ----------
#define SCAN_CHUNK 2048
__global__ void k_scanA() {
    int base = blockIdx.x * SCAN_CHUNK;
    int t = threadIdx.x;
    int s = 0;
    #pragma unroll
    for (int k = 0; k < 8; k++) {
        int idx = base + t * 8 + k;
        if (idx < 3 * NN) {
            s += g_cnt[idx];
            g_dinv[idx] = rsqrtf(g_deg[idx] + 1.0f);
        }
    }
    __shared__ int sh[256];
    sh[t] = s; __syncthreads();
    for (int off = 128; off; off >>= 1) {
        if (t < off) sh[t] += sh[t + off];
        __syncthreads();
    }
    if (t == 0) g_part[blockIdx.x] = sh[0];
}

// ---------------- scan B: one-block shuffle exclusive scan of partials ----------------
__global__ void k_scanB(int nb) {
    int t = threadIdx.x, lane = t & 31, w = t >> 5;
    int v = (t < nb) ? g_part[t] : 0;
    int inc = v;
    #pragma unroll
    for (int off = 1; off < 32; off <<= 1) {
        int nv = __shfl_up_sync(0xffffffffu, inc, off);
        if (lane >= off) inc += nv;
    }
    __shared__ int ws[8];
    if (lane == 31) ws[w] = inc;
    __syncthreads();
    if (t == 0) {
        int run = 0;
        #pragma unroll
        for (int i = 0; i < 8; i++) { int tmp = ws[i]; ws[i] = run; run += tmp; }
    }
    __syncthreads();
    int exc = ws[w] + inc - v;
    if (t < nb) g_part[t] = exc;
    if (t == nb - 1) g_rp[3 * NN] = exc + v;   // == 3*NE
}

// ---------------- scan C: per-chunk exclusive scan -> rowptr ----------------
__global__ void k_scanC() {
    int b = blockIdx.x, t = threadIdx.x;
    int lane = t & 31, w = t >> 5;
    int base = b * SCAN_CHUNK + t * 8;
    int v[8]; int s = 0;
    #pragma unroll
    for (int k = 0; k < 8; k++) {
        int idx = base + k;
        v[k] = (idx < 3 * NN) ? g_cnt[idx] : 0;
    }
    #pragma unroll
    for (int k = 0; k < 8; k++) { int tmp = v[k]; v[k] = s; s += tmp; }
    int inc = s;
    #pragma unroll
    for (int off = 1; off < 32; off <<= 1) {
        int nv = __shfl_up_sync(0xffffffffu, inc, off);
        if (lane >= off) inc += nv;
    }
    int texc = inc - s;
    __shared__ int wsum[8];
    if (lane == 31) wsum[w] = inc;
    __syncthreads();
    if (t == 0) {
        int run = 0;
        #pragma unroll
        for (int i = 0; i < 8; i++) { int tmp = wsum[i]; wsum[i] = run; run += tmp; }
    }
    __syncthreads();
    int off0 = g_part[b] + wsum[w] + texc;
    #pragma unroll
    for (int k = 0; k < 8; k++) {
        int idx = base + k;
        if (idx < 3 * NN) g_rp[idx] = off0 + v[k];
    }
}

// ---------------- pass 2 over edges: atomic-free scatter into CSR order ----------------
__global__ void k_scatter(const float* ea0, const float* ea1, const float* ea2) {
    int i = blockIdx.x * blockDim.x + threadIdx.x;
    if (i >= NE) return;
    int g = blockIdx.y;
    const float* ea = (g == 0) ? ea0 : (g == 1) ? ea1 : ea2;
    long long e = (long long)g * NE + i;
    int2 sc = g_srccol[e];
    float nrm = g_dinv[g * NN + sc.x] * ea[i] * g_dinv[g * NN + sc.y];
    int pos = g_rp[g * NN + sc.y] + g_rank[e];
    g_edges[pos] = make_int2(sc.x, __float_as_int(nrm));
}

// ---------------- dense GEMM: feat16[g] = X_g[N,K] @ W_g[K,32], grid.y = graph ----------
template<int K, bool USEH>
__global__ void __launch_bounds__(256) k_gemm(const float* __restrict__ X0,
                                              const float* __restrict__ X1,
                                              const float* __restrict__ X2,
                                              const float* __restrict__ W0,
                                              const float* __restrict__ W1,
                                              const float* __restrict__ W2) {
    __shared__ float Wsh[K * HID];
    __shared__ float Xs[32 * (K + 4)];
    int g = blockIdx.y;
    const float* X = USEH ? (const float*)g_h
                          : ((g == 0) ? X0 : (g == 1) ? X1 : X2);
    const float* Wm = (g == 0) ? W0 : (g == 1) ? W1 : W2;
    __half* Y = g_feat[g];
    int t = threadIdx.x;
    for (int i = t; i < K * HID; i += 256) Wsh[i] = Wm[i];
    const float* xb = X + (size_t)blockIdx.x * 32 * K;
    for (int i = t; i < 32 * K; i += 256) {
        int r = i / K, k = i - r * K;
        Xs[r * (K + 4) + k] = xb[i];
    }
    __syncthreads();
    int w = t >> 5, lane = t & 31;
    int r = w * 4 + (lane >> 3);
    int cq = lane & 7;
    const float* xrow = &Xs[r * (K + 4)];
    float4 acc = make_float4(0.f, 0.f, 0.f, 0.f);
    #pragma unroll 16
    for (int k = 0; k < K; k++) {
        float xk = xrow[k];
        float4 wv = *(const float4*)&Wsh[k * HID + cq * 4];
        acc.x = fmaf(xk, wv.x, acc.x);
        acc.y = fmaf(xk, wv.y, acc.y);
        acc.z = fmaf(xk, wv.z, acc.z);
        acc.w = fmaf(xk, wv.w, acc.w);
    }
    size_t gr = (size_t)blockIdx.x * 32 + r;
    __half2 h01 = __floats2half2_rn(acc.x, acc.y);
    __half2 h23 = __floats2half2_rn(acc.z, acc.w);
    uint2 pk = make_uint2(*(unsigned int*)&h01, *(unsigned int*)&h23);
    *(uint2*)&Y[gr * HID + cq * 4] = pk;     // 8B aligned: 64B/row, cq*8 byte offset
}

// ---------------- CSR gather over fp16 rows, unrolled x8 (lane j = feature dim) --------
__device__ __forceinline__ float gather_seg(const __half* __restrict__ H, int s, int e2, int j) {
    float a = 0.f;
    int e = s;
    for (; e + 8 <= e2; e += 8) {
        int2 p[8];
        #pragma unroll
        for (int k = 0; k < 8; k++) p[k] = g_edges[e + k];
        float v[8];
        #pragma unroll
        for (int k = 0; k < 8; k++) v[k] = __half2float(__ldg(&H[p[k].x * HID + j]));
        #pragma unroll
        for (int k = 0; k < 8; k++) a = fmaf(__int_as_float(p[k].y), v[k], a);
    }
    if (e + 4 <= e2) {
        int2 p[4];
        #pragma unroll
        for (int k = 0; k < 4; k++) p[k] = g_edges[e + k];
        float v[4];
        #pragma unroll
        for (int k = 0; k < 4; k++) v[k] = __half2float(__ldg(&H[p[k].x * HID + j]));
        #pragma unroll
        for (int k = 0; k < 4; k++) a = fmaf(__int_as_float(p[k].y), v[k], a);
        e += 4;
    }
    for (; e < e2; e++) {
        int2 p = g_edges[e];
        a = fmaf(__int_as_float(p.y), __half2float(__ldg(&H[p.x * HID + j])), a);
    }
    return a;
}

// ---------------- layer 1: 3x conv + relu + attention + combine ----------------
__global__ void __launch_bounds__(256) k_conv1(const float* __restrict__ b0,
                                               const float* __restrict__ b1,
                                               const float* __restrict__ b2,
                                               const float* __restrict__ attw,
                                               float* __restrict__ wout) {
    int c = blockIdx.x * 8 + (threadIdx.x >> 5);
    int j = threadIdx.x & 31;
    if (c >= NN) return;
    float acc[3];
    #pragma unroll
    for (int g = 0; g < 3; g++) {
        const __half* H = g_feat[g];
        int s = g_rp[g * NN + c], e2 = g_rp[g * NN + c + 1];
        float a = gather_seg(H, s, e2, j);
        float di = g_dinv[g * NN + c];
        a = fmaf(di * di, __half2float(H[c * HID + j]), a);   // self loop (weight 1)
        acc[g] = a;
    }
    acc[0] += b0[j]; acc[1] += b1[j]; acc[2] += b2[j];
    acc[0] = fmaxf(acc[0], 0.f);
    acc[1] = fmaxf(acc[1], 0.f);
    acc[2] = fmaxf(acc[2], 0.f);
    float attj = attw[j];
    float cf[3];
    #pragma unroll
    for (int g = 0; g < 3; g++) {
        float v = acc[g] * attj;
        v += __shfl_xor_sync(0xffffffffu, v, 16);
        v += __shfl_xor_sync(0xffffffffu, v, 8);
        v += __shfl_xor_sync(0xffffffffu, v, 4);
        v += __shfl_xor_sync(0xffffffffu, v, 2);
        v += __shfl_xor_sync(0xffffffffu, v, 1);
        v = (v > 0.f) ? v : 0.01f * v;          // jax.nn.leaky_relu default slope
        cf[g] = expf(v);
    }
    float inv = 1.0f / (cf[0] + cf[1] + cf[2]);
    float w0 = cf[0] * inv, w1 = cf[1] * inv, w2 = cf[2] * inv;
    g_h[c * HID + j] = w0 * acc[0] + w1 * acc[1] + w2 * acc[2];
    if (j == 0) { wout[c] = w0; wout[NN + c] = w1; wout[2 * NN + c] = w2; }
}

// ---------------- layer 2: sum of 3 convs ----------------
__global__ void __launch_bounds__(256) k_conv2(const float* __restrict__ bo0,
                                               const float* __restrict__ bo1,
                                               const float* __restrict__ bo2,
                                               float* __restrict__ out) {
    int c = blockIdx.x * 8 + (threadIdx.x >> 5);
    int j = threadIdx.x & 31;
    if (c >= NN) return;
    float a = bo0[j] + bo1[j] + bo2[j];
    #pragma unroll
    for (int g = 0; g < 3; g++) {
        const __half* H = g_feat[g];
        int s = g_rp[g * NN + c], e2 = g_rp[g * NN + c + 1];
        a += gather_seg(H, s, e2, j);
        float di = g_dinv[g * NN + c];
        a = fmaf(di * di, __half2float(H[c * HID + j]), a);
    }
    out[c * HID + j] = a;
}

// ---------------- host launch ----------------
extern "C" void kernel_launch(void* const* d_in, const int* in_sizes, int n_in,
                              void* d_out, int out_size) {
    const float *x[3], *ea[3], *W[3], *b[3], *Wo[3], *bo[3], *attw;
    const void *ei[3];

    bool interleaved = (in_sizes[1] == 2 * NE);   // dict order: x1,ei1,ea1,W1,b1,Wo1,bo1,...
    if (interleaved) {
        for (int g = 0; g < 3; g++) {
            int base = g * 7;
            x[g]  = (const float*)d_in[base + 0];
            ei[g] = d_in[base + 1];
            ea[g] = (const float*)d_in[base + 2];
            W[g]  = (const float*)d_in[base + 3];
            b[g]  = (const float*)d_in[base + 4];
            Wo[g] = (const float*)d_in[base + 5];
            bo[g] = (const float*)d_in[base + 6];
        }
        attw = (const float*)d_in[21];
    } else {                                       // signature order: x1,x2,x3,ei1..ei3,...
        for (int g = 0; g < 3; g++) {
            x[g]  = (const float*)d_in[g];
            ei[g] = d_in[3 + g];
            ea[g] = (const float*)d_in[6 + g];
            W[g]  = (const float*)d_in[9 + g];
            b[g]  = (const float*)d_in[12 + g];
            Wo[g] = (const float*)d_in[15 + g];
            bo[g] = (const float*)d_in[18 + g];
        }
        attw = (const float*)d_in[21];
    }

    float* out  = (float*)d_out;
    float* wout = out + (size_t)NN * HID;

    const int eblocks = (NE + 255) / 256;
    const int nblocks3N = (3 * NN + 255) / 256;
    const int NB = (3 * NN + SCAN_CHUNK - 1) / SCAN_CHUNK;   // 147
    const int conv_blocks = (NN + 7) / 8;                     // 12500
    dim3 egrid(eblocks, 3, 1);
    dim3 ggrid(NN / 32, 3, 1);                                // 3125 x 3

    // Launch order chosen so index 3 (the ncu -s window) = the K=128 GEMM.
    k_init<<<nblocks3N, 256>>>((const long long*)ei[0]);                       // 0
    k_count<<<egrid, 256>>>(ei[0], ei[1], ei[2], ea[0], ea[1], ea[2]);         // 1
    k_scanA<<<NB, 256>>>();                                                    // 2
    k_gemm<KIN, false><<<ggrid, 256>>>(x[0], x[1], x[2], W[0], W[1], W[2]);    // 3 (profiled)
    k_scanB<<<1, 256>>>(NB);                                                   // 4
    k_scanC<<<NB, 256>>>();                                                    // 5
    k_scatter<<<egrid, 256>>>(ea[0], ea[1], ea[2]);                            // 6
    k_conv1<<<conv_blocks, 256>>>(b[0], b[1], b[2], attw, wout);               // 7
    k_gemm<HID, true><<<ggrid, 256>>>(nullptr, nullptr, nullptr,
                                      Wo[0], Wo[1], Wo[2]);                    // 8
    k_conv2<<<conv_blocks, 256>>>(bo[0], bo[1], bo[2], out);                   // 9
}

// round 10
// speedup vs baseline: 1.4079x; 1.2446x over previous
#include <cuda_runtime.h>
#include <cuda_fp16.h>
#include <math.h>

#define NN 100000
#define NE 1600000
#define HID 32
#define KIN 128

// ---------------- device scratch (allocation-free: __device__ globals) ----------------
__device__ float  g_deg[3 * NN];          // weighted in-degree (w/o self loop)
__device__ float  g_dinv[3 * NN];         // rsqrt(deg + 1)
__device__ int    g_cnt[3 * NN];          // per-dest edge counts
__device__ int    g_rp[3 * NN + 1];       // exclusive scan of g_cnt (global CSR rowptr)
__device__ int    g_part[256];            // scan partials
__device__ int    g_rank[3 * NE];         // edge rank within its dest (from count pass)
__device__ int2   g_srccol[3 * NE];       // int32 (src, col) per edge (from count pass)
__device__ int2   g_edges[3 * NE];        // CSR-ordered (src, norm-as-int) per dest
__device__ __half g_feat[3][NN * HID];    // xw_g (layer1) then hw_g (layer2), fp16
__device__ float  g_h[NN * HID];          // combined hidden (fp32)
__device__ int    g_is64;                 // edge index dtype flag

// ---------------- init: zero scratch + dtype detect (block 0) ----------------
__global__ void k_init(const long long* ei) {
    int i = blockIdx.x * blockDim.x + threadIdx.x;
    if (i < 3 * NN) { g_deg[i] = 0.f; g_cnt[i] = 0; }
    if (blockIdx.x == 0) {
        __shared__ int ok;
        if (threadIdx.x == 0) ok = 1;
        __syncthreads();
        for (int k = threadIdx.x; k < 4096; k += 256) {
            long long v = ei[k];
            if (v < 0 || v >= NN) ok = 0;   // int32 data read as int64 -> out-of-range
        }
        __syncthreads();
        if (threadIdx.x == 0) g_is64 = ok;
    }
}

__device__ __forceinline__ int load_idx(const void* eiv, long long pos) {
    if (g_is64) return (int)((const long long*)eiv)[pos];
    return ((const int*)eiv)[pos];
}

// ---------------- pass 1 over edges: degree + count + persist rank/src/col ----------------
__global__ void k_count(const void* ei0, const void* ei1, const void* ei2,
                        const float* ea0, const float* ea1, const float* ea2) {
    int i = blockIdx.x * blockDim.x + threadIdx.x;
    if (i >= NE) return;
    int g = blockIdx.y;
    const void* eiv = (g == 0) ? ei0 : (g == 1) ? ei1 : ei2;
    const float* ea = (g == 0) ? ea0 : (g == 1) ? ea1 : ea2;
    int r = load_idx(eiv, i);
    int c = load_idx(eiv, (long long)NE + i);
    atomicAdd(&g_deg[g * NN + c], ea[i]);
    int rank = atomicAdd(&g_cnt[g * NN + c], 1);
    long long e = (long long)g * NE + i;
    g_rank[e] = rank;
    g_srccol[e] = make_int2(r, c);
}

// ---------------- scan A: per-chunk sums of g_cnt + dinv (fused, same 3N sweep) ----------
#define SCAN_CHUNK 2048
__global__ void k_scanA() {
    int base = blockIdx.x * SCAN_CHUNK;
    int t = threadIdx.x;
    int s = 0;
    #pragma unroll
    for (int k = 0; k < 8; k++) {
        int idx = base + t * 8 + k;
        if (idx < 3 * NN) {
            s += g_cnt[idx];
            g_dinv[idx] = rsqrtf(g_deg[idx] + 1.0f);
        }
    }
    __shared__ int sh[256];
    sh[t] = s; __syncthreads();
    for (int off = 128; off; off >>= 1) {
        if (t < off) sh[t] += sh[t + off];
        __syncthreads();
    }
    if (t == 0) g_part[blockIdx.x] = sh[0];
}

// ---------------- scan B: one-block shuffle exclusive scan of partials ----------------
__global__ void k_scanB(int nb) {
    int t = threadIdx.x, lane = t & 31, w = t >> 5;
    int v = (t < nb) ? g_part[t] : 0;
    int inc = v;
    #pragma unroll
    for (int off = 1; off < 32; off <<= 1) {
        int nv = __shfl_up_sync(0xffffffffu, inc, off);
        if (lane >= off) inc += nv;
    }
    __shared__ int ws[8];
    if (lane == 31) ws[w] = inc;
    __syncthreads();
    if (t == 0) {
        int run = 0;
        #pragma unroll
        for (int i = 0; i < 8; i++) { int tmp = ws[i]; ws[i] = run; run += tmp; }
    }
    __syncthreads();
    int exc = ws[w] + inc - v;
    if (t < nb) g_part[t] = exc;
    if (t == nb - 1) g_rp[3 * NN] = exc + v;   // == 3*NE
}

// ---------------- scan C: per-chunk exclusive scan -> rowptr ----------------
__global__ void k_scanC() {
    int b = blockIdx.x, t = threadIdx.x;
    int lane = t & 31, w = t >> 5;
    int base = b * SCAN_CHUNK + t * 8;
    int v[8]; int s = 0;
    #pragma unroll
    for (int k = 0; k < 8; k++) {
        int idx = base + k;
        v[k] = (idx < 3 * NN) ? g_cnt[idx] : 0;
    }
    #pragma unroll
    for (int k = 0; k < 8; k++) { int tmp = v[k]; v[k] = s; s += tmp; }
    int inc = s;
    #pragma unroll
    for (int off = 1; off < 32; off <<= 1) {
        int nv = __shfl_up_sync(0xffffffffu, inc, off);
        if (lane >= off) inc += nv;
    }
    int texc = inc - s;
    __shared__ int wsum[8];
    if (lane == 31) wsum[w] = inc;
    __syncthreads();
    if (t == 0) {
        int run = 0;
        #pragma unroll
        for (int i = 0; i < 8; i++) { int tmp = wsum[i]; wsum[i] = run; run += tmp; }
    }
    __syncthreads();
    int off0 = g_part[b] + wsum[w] + texc;
    #pragma unroll
    for (int k = 0; k < 8; k++) {
        int idx = base + k;
        if (idx < 3 * NN) g_rp[idx] = off0 + v[k];
    }
}

// ---------------- pass 2 over edges: atomic-free scatter into CSR order ----------------
__global__ void k_scatter(const float* ea0, const float* ea1, const float* ea2) {
    int i = blockIdx.x * blockDim.x + threadIdx.x;
    if (i >= NE) return;
    int g = blockIdx.y;
    const float* ea = (g == 0) ? ea0 : (g == 1) ? ea1 : ea2;
    long long e = (long long)g * NE + i;
    int2 sc = g_srccol[e];
    float nrm = g_dinv[g * NN + sc.x] * ea[i] * g_dinv[g * NN + sc.y];
    int pos = g_rp[g * NN + sc.y] + g_rank[e];
    g_edges[pos] = make_int2(sc.x, __float_as_int(nrm));
}

// ---------------- register-blocked GEMM: feat16[g] = X_g[N,K] @ W_g[K,32] ---------------
// Block = 64 rows, 8 warps; warp computes 8 rows x 32 cols (lane = col, 8 accumulators).
// X staged TRANSPOSED in smem so per-k x reads are uniform-address LDS.128 broadcasts
// (1 wavefront) and W reads are lane-indexed scalar LDS (conflict-free, 1 wavefront):
// 3 wavefronts / 256 FLOP vs 10 in the old layout -> FFMA-bound.
template<int K, bool USEH>
__global__ void __launch_bounds__(256) k_gemm(const float* __restrict__ X0,
                                              const float* __restrict__ X1,
                                              const float* __restrict__ X2,
                                              const float* __restrict__ W0,
                                              const float* __restrict__ W1,
                                              const float* __restrict__ W2) {
    constexpr int ROWS = 64;
    constexpr int LDX  = ROWS + 4;    // 68 floats = 272B per k-row: 16B-aligned slices
    __shared__ float Wsh[K * HID];
    __shared__ float Xs[K * LDX];
    int g = blockIdx.y;
    const float* X = USEH ? (const float*)g_h
                          : ((g == 0) ? X0 : (g == 1) ? X1 : X2);
    const float* Wm = (g == 0) ? W0 : (g == 1) ? W1 : W2;
    __half* Y = g_feat[g];
    int t = threadIdx.x;
    for (int i = t; i < K * HID; i += 256) Wsh[i] = Wm[i];
    int row0 = blockIdx.x * ROWS;
    for (int i = t; i < ROWS * K; i += 256) {
        int r = i / K, k = i - r * K;
        int gr = row0 + r;
        Xs[k * LDX + r] = (gr < NN) ? X[(size_t)gr * K + k] : 0.f;
    }
    __syncthreads();
    int w = t >> 5, lane = t & 31;
    int rbase = w * 8;
    float acc[8];
    #pragma unroll
    for (int r = 0; r < 8; r++) acc[r] = 0.f;
    const float* wp = &Wsh[lane];
    const float* xp = &Xs[rbase];
    #pragma unroll 4
    for (int k = 0; k < K; k++) {
        float wv = wp[k * HID];
        float4 xa = *(const float4*)&xp[k * LDX];
        float4 xb = *(const float4*)&xp[k * LDX + 4];
        acc[0] = fmaf(xa.x, wv, acc[0]);
        acc[1] = fmaf(xa.y, wv, acc[1]);
        acc[2] = fmaf(xa.z, wv, acc[2]);
        acc[3] = fmaf(xa.w, wv, acc[3]);
        acc[4] = fmaf(xb.x, wv, acc[4]);
        acc[5] = fmaf(xb.y, wv, acc[5]);
        acc[6] = fmaf(xb.z, wv, acc[6]);
        acc[7] = fmaf(xb.w, wv, acc[7]);
    }
    #pragma unroll
    for (int r = 0; r < 8; r++) {
        int gr = row0 + rbase + r;
        if (gr < NN) Y[(size_t)gr * HID + lane] = __float2half_rn(acc[r]);
    }
}

// ---------------- CSR gather over fp16 rows, unrolled x8 (lane j = feature dim) --------
__device__ __forceinline__ float gather_seg(const __half* __restrict__ H, int s, int e2, int j) {
    float a = 0.f;
    int e = s;
    for (; e + 8 <= e2; e += 8) {
        int2 p[8];
        #pragma unroll
        for (int k = 0; k < 8; k++) p[k] = g_edges[e + k];
        float v[8];
        #pragma unroll
        for (int k = 0; k < 8; k++) v[k] = __half2float(__ldg(&H[p[k].x * HID + j]));
        #pragma unroll
        for (int k = 0; k < 8; k++) a = fmaf(__int_as_float(p[k].y), v[k], a);
    }
    if (e + 4 <= e2) {
        int2 p[4];
        #pragma unroll
        for (int k = 0; k < 4; k++) p[k] = g_edges[e + k];
        float v[4];
        #pragma unroll
        for (int k = 0; k < 4; k++) v[k] = __half2float(__ldg(&H[p[k].x * HID + j]));
        #pragma unroll
        for (int k = 0; k < 4; k++) a = fmaf(__int_as_float(p[k].y), v[k], a);
        e += 4;
    }
    for (; e < e2; e++) {
        int2 p = g_edges[e];
        a = fmaf(__int_as_float(p.y), __half2float(__ldg(&H[p.x * HID + j])), a);
    }
    return a;
}

// ---------------- layer 1: 3x conv + relu + attention + combine ----------------
__global__ void __launch_bounds__(256) k_conv1(const float* __restrict__ b0,
                                               const float* __restrict__ b1,
                                               const float* __restrict__ b2,
                                               const float* __restrict__ attw,
                                               float* __restrict__ wout) {
    int c = blockIdx.x * 8 + (threadIdx.x >> 5);
    int j = threadIdx.x & 31;
    if (c >= NN) return;
    float acc[3];
    #pragma unroll
    for (int g = 0; g < 3; g++) {
        const __half* H = g_feat[g];
        int s = g_rp[g * NN + c], e2 = g_rp[g * NN + c + 1];
        float a = gather_seg(H, s, e2, j);
        float di = g_dinv[g * NN + c];
        a = fmaf(di * di, __half2float(H[c * HID + j]), a);   // self loop (weight 1)
        acc[g] = a;
    }
    acc[0] += b0[j]; acc[1] += b1[j]; acc[2] += b2[j];
    acc[0] = fmaxf(acc[0], 0.f);
    acc[1] = fmaxf(acc[1], 0.f);
    acc[2] = fmaxf(acc[2], 0.f);
    float attj = attw[j];
    float cf[3];
    #pragma unroll
    for (int g = 0; g < 3; g++) {
        float v = acc[g] * attj;
        v += __shfl_xor_sync(0xffffffffu, v, 16);
        v += __shfl_xor_sync(0xffffffffu, v, 8);
        v += __shfl_xor_sync(0xffffffffu, v, 4);
        v += __shfl_xor_sync(0xffffffffu, v, 2);
        v += __shfl_xor_sync(0xffffffffu, v, 1);
        v = (v > 0.f) ? v : 0.01f * v;          // jax.nn.leaky_relu default slope
        cf[g] = expf(v);
    }
    float inv = 1.0f / (cf[0] + cf[1] + cf[2]);
    float w0 = cf[0] * inv, w1 = cf[1] * inv, w2 = cf[2] * inv;
    g_h[c * HID + j] = w0 * acc[0] + w1 * acc[1] + w2 * acc[2];
    if (j == 0) { wout[c] = w0; wout[NN + c] = w1; wout[2 * NN + c] = w2; }
}

// ---------------- layer 2: sum of 3 convs ----------------
__global__ void __launch_bounds__(256) k_conv2(const float* __restrict__ bo0,
                                               const float* __restrict__ bo1,
                                               const float* __restrict__ bo2,
                                               float* __restrict__ out) {
    int c = blockIdx.x * 8 + (threadIdx.x >> 5);
    int j = threadIdx.x & 31;
    if (c >= NN) return;
    float a = bo0[j] + bo1[j] + bo2[j];
    #pragma unroll
    for (int g = 0; g < 3; g++) {
        const __half* H = g_feat[g];
        int s = g_rp[g * NN + c], e2 = g_rp[g * NN + c + 1];
        a += gather_seg(H, s, e2, j);
        float di = g_dinv[g * NN + c];
        a = fmaf(di * di, __half2float(H[c * HID + j]), a);
    }
    out[c * HID + j] = a;
}

// ---------------- host launch ----------------
extern "C" void kernel_launch(void* const* d_in, const int* in_sizes, int n_in,
                              void* d_out, int out_size) {
    const float *x[3], *ea[3], *W[3], *b[3], *Wo[3], *bo[3], *attw;
    const void *ei[3];

    bool interleaved = (in_sizes[1] == 2 * NE);   // dict order: x1,ei1,ea1,W1,b1,Wo1,bo1,...
    if (interleaved) {
        for (int g = 0; g < 3; g++) {
            int base = g * 7;
            x[g]  = (const float*)d_in[base + 0];
            ei[g] = d_in[base + 1];
            ea[g] = (const float*)d_in[base + 2];
            W[g]  = (const float*)d_in[base + 3];
            b[g]  = (const float*)d_in[base + 4];
            Wo[g] = (const float*)d_in[base + 5];
            bo[g] = (const float*)d_in[base + 6];
        }
        attw = (const float*)d_in[21];
    } else {                                       // signature order: x1,x2,x3,ei1..ei3,...
        for (int g = 0; g < 3; g++) {
            x[g]  = (const float*)d_in[g];
            ei[g] = d_in[3 + g];
            ea[g] = (const float*)d_in[6 + g];
            W[g]  = (const float*)d_in[9 + g];
            b[g]  = (const float*)d_in[12 + g];
            Wo[g] = (const float*)d_in[15 + g];
            bo[g] = (const float*)d_in[18 + g];
        }
        attw = (const float*)d_in[21];
    }

    float* out  = (float*)d_out;
    float* wout = out + (size_t)NN * HID;

    const int eblocks = (NE + 255) / 256;
    const int nblocks3N = (3 * NN + 255) / 256;
    const int NB = (3 * NN + SCAN_CHUNK - 1) / SCAN_CHUNK;   // 147
    const int conv_blocks = (NN + 7) / 8;                     // 12500
    dim3 egrid(eblocks, 3, 1);
    dim3 ggrid((NN + 63) / 64, 3, 1);                         // 1563 x 3

    // Launch order keeps index 3 (the ncu -s window) = the K=128 GEMM.
    k_init<<<nblocks3N, 256>>>((const long long*)ei[0]);                       // 0
    k_count<<<egrid, 256>>>(ei[0], ei[1], ei[2], ea[0], ea[1], ea[2]);         // 1
    k_scanA<<<NB, 256>>>();                                                    // 2
    k_gemm<KIN, false><<<ggrid, 256>>>(x[0], x[1], x[2], W[0], W[1], W[2]);    // 3 (profiled)
    k_scanB<<<1, 256>>>(NB);                                                   // 4
    k_scanC<<<NB, 256>>>();                                                    // 5
    k_scatter<<<egrid, 256>>>(ea[0], ea[1], ea[2]);                            // 6
    k_conv1<<<conv_blocks, 256>>>(b[0], b[1], b[2], attw, wout);               // 7
    k_gemm<HID, true><<<ggrid, 256>>>(nullptr, nullptr, nullptr,
                                      Wo[0], Wo[1], Wo[2]);                    // 8
    k_conv2<<<conv_blocks, 256>>>(bo[0], bo[1], bo[2], out);                   // 9
}